// round 8
// baseline (speedup 1.0000x reference)
#include <cuda_runtime.h>
#include <cuda_bf16.h>

// Problem constants
#define B_      2
#define L_      64
#define D_      1024
#define H_      512
#define S_      50000
#define V_      40000
#define K_      32
#define M_      128          // B_*L_
#define SLM_SCALE 0.1f
#define BN_EPS  1e-5f

typedef unsigned long long ull;

// ---------------- f32x2 packed helpers ----------------
static __device__ __forceinline__ ull pack2(float x, float y) {
    ull r; asm("mov.b64 %0, {%1, %2};" : "=l"(r) : "f"(x), "f"(y)); return r;
}
static __device__ __forceinline__ void unpack2(ull v, float& x, float& y) {
    asm("mov.b64 {%0, %1}, %2;" : "=f"(x), "=f"(y) : "l"(v));
}
static __device__ __forceinline__ void ffma2(ull& d, ull a, ull b) {
    asm("fma.rn.f32x2 %0, %1, %2, %0;" : "+l"(d) : "l"(a), "l"(b));
}

// ---------------- scratch (device globals; no allocation allowed) ----------------
__device__ float g_scale[L_];
__device__ float g_shift[L_];
__device__ __align__(16) float g_ht[H_ * M_];          // h^T : [512][128]
__device__ __align__(16) float g_vt[V_ * M_];          // v^T : [40000][128] (20.5 MB, L2-resident)

// ---------------- Kernel 1: BatchNorm stats over (B, D) per position l ----------------
__global__ __launch_bounds__(256)
void bn_stats_kernel(const float* __restrict__ x,
                     const float* __restrict__ gamma,
                     const float* __restrict__ beta)
{
    const int l = blockIdx.x;
    const float* p0 = x + (size_t)l * D_;             // b = 0
    const float* p1 = x + (size_t)(L_ + l) * D_;      // b = 1
    float s = 0.f, sq = 0.f;
    for (int i = threadIdx.x; i < D_; i += 256) {
        float a = p0[i], b = p1[i];
        s  += a + b;
        sq += a * a + b * b;
    }
    __shared__ float rs[256], rq[256];
    rs[threadIdx.x] = s; rq[threadIdx.x] = sq;
    __syncthreads();
    for (int off = 128; off > 0; off >>= 1) {
        if (threadIdx.x < off) {
            rs[threadIdx.x] += rs[threadIdx.x + off];
            rq[threadIdx.x] += rq[threadIdx.x + off];
        }
        __syncthreads();
    }
    if (threadIdx.x == 0) {
        const float inv_n = 1.f / (float)(B_ * D_);
        float mean = rs[0] * inv_n;
        float var  = rq[0] * inv_n - mean * mean;
        float rstd = rsqrtf(var + BN_EPS);
        float sc = gamma[l] * rstd;
        g_scale[l] = sc;
        g_shift[l] = beta[l] - mean * sc;
    }
}

// ---------------- Kernel 2: h = relu(xn @ W1 + b1), stored transposed ----------------
__global__ __launch_bounds__(256)
void h_gemm_kernel(const float* __restrict__ x,
                   const float* __restrict__ W1,
                   const float* __restrict__ b1)
{
    __shared__ float sSc[64], sSh[64];
    __shared__ float Ast[64 * 33];
    __shared__ float Bst[32 * 32];
    const int tid = threadIdx.x;
    const int m0 = blockIdx.x * 64;
    const int n0 = blockIdx.y * 32;
    if (tid < 64) { sSc[tid] = g_scale[tid]; sSh[tid] = g_shift[tid]; }
    __syncthreads();
    const int mg = tid >> 4;
    const int ng = tid & 15;
    float acc[4][2] = {};
    for (int k0 = 0; k0 < D_; k0 += 32) {
        #pragma unroll
        for (int i = 0; i < 8; ++i) {
            int e = tid + i * 256;
            int mi = e >> 5, ki = e & 31;
            float v = x[(size_t)(m0 + mi) * D_ + k0 + ki];
            Ast[mi * 33 + ki] = v * sSc[mi] + sSh[mi];
        }
        #pragma unroll
        for (int i = 0; i < 4; ++i) {
            int e = tid + i * 256;
            int ki = e >> 5, ni = e & 31;
            Bst[ki * 32 + ni] = W1[(size_t)(k0 + ki) * H_ + n0 + ni];
        }
        __syncthreads();
        #pragma unroll
        for (int kk = 0; kk < 32; ++kk) {
            float b0 = Bst[kk * 32 + ng * 2];
            float b1v = Bst[kk * 32 + ng * 2 + 1];
            #pragma unroll
            for (int i = 0; i < 4; ++i) {
                float a = Ast[(mg * 4 + i) * 33 + kk];
                acc[i][0] = fmaf(a, b0, acc[i][0]);
                acc[i][1] = fmaf(a, b1v, acc[i][1]);
            }
        }
        __syncthreads();
    }
    #pragma unroll
    for (int j = 0; j < 2; ++j) {
        int n = n0 + ng * 2 + j;
        float bb = b1[n];
        #pragma unroll
        for (int i = 0; i < 4; ++i) {
            int m = m0 + mg * 4 + i;
            float hv = acc[i][j] + bb;
            g_ht[(size_t)n * M_ + m] = fmaxf(hv, 0.f);
        }
    }
}

// ---------------- Kernels 3 & 4: big GEMMs via packed fma.rn.f32x2 ----------------
// 256 threads, tile M=128 x N=128, KC=16, thread tile 8m x 8n.
// acc pairs packed along M: acc2[i2][j] holds (m = r*8+2*i2, +1) for col c*8+j.
// MODE 0: v^T = (h @ W_slm + b_slm)^T   -> g_vt  (fp32)
// MODE 1: out = h @ W2 + b2 + 0.1 * gather(v^T)  (gather fused into acc)
template<int MODE>
__global__ __launch_bounds__(256, 2)
void big_gemm_kernel(const float* __restrict__ W,
                     const float* __restrict__ bias,
                     const float* __restrict__ slw,
                     const int*   __restrict__ slidx,
                     float* __restrict__ out,
                     int Nfull)
{
    // 32 KB pool: double-buffered A|B tiles in mainloop; reused for idx/weight in MODE1 epilogue
    __shared__ __align__(16) float s_pool[2 * 4096];

    const int tid = threadIdx.x;
    const int r = tid >> 4;           // 0..15 -> m base r*8
    const int c = tid & 15;           // 0..15 -> n base c*8
    const int n0 = blockIdx.x * 128;

    ull acc2[4][8];
    #pragma unroll
    for (int i = 0; i < 4; ++i)
        #pragma unroll
        for (int j = 0; j < 8; ++j) acc2[i][j] = 0ULL;

    // staged-register prefetch
    float4 pa0, pa1, pb0, pb1;
    {
        const float4* Ag4 = (const float4*)g_ht;           // k0 = 0
        pa0 = Ag4[tid]; pa1 = Ag4[tid + 256];
        #pragma unroll
        for (int i = 0; i < 2; ++i) {
            int e = tid + i * 256;
            int ki = e >> 5, n = n0 + (e & 31) * 4;
            float4 bv = make_float4(0.f, 0.f, 0.f, 0.f);
            if (n < Nfull) bv = *(const float4*)(W + (size_t)ki * Nfull + n);
            if (i == 0) pb0 = bv; else pb1 = bv;
        }
    }

    int buf = 0;
    for (int k0 = 0; k0 < H_; k0 += 16) {
        float* base = s_pool + buf * 4096;
        float4* As4 = (float4*)base;
        float4* Bs4 = (float4*)(base + 2048);
        As4[tid] = pa0; As4[tid + 256] = pa1;
        Bs4[tid] = pb0; Bs4[tid + 256] = pb1;
        __syncthreads();

        if (k0 + 16 < H_) {
            const int nk0 = k0 + 16;
            const float4* Ag4 = (const float4*)(g_ht + (size_t)nk0 * M_);
            pa0 = Ag4[tid]; pa1 = Ag4[tid + 256];
            #pragma unroll
            for (int i = 0; i < 2; ++i) {
                int e = tid + i * 256;
                int ki = e >> 5, n = n0 + (e & 31) * 4;
                float4 bv = make_float4(0.f, 0.f, 0.f, 0.f);
                if (n < Nfull) bv = *(const float4*)(W + (size_t)(nk0 + ki) * Nfull + n);
                if (i == 0) pb0 = bv; else pb1 = bv;
            }
        }

        #pragma unroll
        for (int kk = 0; kk < 16; ++kk) {
            const float4 a0 = As4[kk * 32 + r * 2];
            const float4 a1 = As4[kk * 32 + r * 2 + 1];
            const float4 b0 = Bs4[kk * 32 + c * 2];
            const float4 b1v = Bs4[kk * 32 + c * 2 + 1];
            ull ap[4] = { pack2(a0.x, a0.y), pack2(a0.z, a0.w),
                          pack2(a1.x, a1.y), pack2(a1.z, a1.w) };
            ull bd[8] = { pack2(b0.x, b0.x), pack2(b0.y, b0.y),
                          pack2(b0.z, b0.z), pack2(b0.w, b0.w),
                          pack2(b1v.x, b1v.x), pack2(b1v.y, b1v.y),
                          pack2(b1v.z, b1v.z), pack2(b1v.w, b1v.w) };
            #pragma unroll
            for (int j = 0; j < 8; ++j)
                #pragma unroll
                for (int i2 = 0; i2 < 4; ++i2)
                    ffma2(acc2[i2][j], ap[i2], bd[j]);
        }
        __syncthreads();
        buf ^= 1;
    }

    if (MODE == 0) {
        // store v^T (+ b_slm): thread (r,c) writes cols m=r*8..+7 of rows n=c*8..+7
        #pragma unroll
        for (int j = 0; j < 8; ++j) {
            int n = n0 + c * 8 + j;
            if (n < Nfull) {
                float bs = bias[n];
                float x0, x1, x2, x3, x4, x5, x6, x7;
                unpack2(acc2[0][j], x0, x1);
                unpack2(acc2[1][j], x2, x3);
                unpack2(acc2[2][j], x4, x5);
                unpack2(acc2[3][j], x6, x7);
                float* dst = g_vt + (size_t)n * M_ + r * 8;
                *(float4*)dst       = make_float4(x0 + bs, x1 + bs, x2 + bs, x3 + bs);
                *(float4*)(dst + 4) = make_float4(x4 + bs, x5 + bs, x6 + bs, x7 + bs);
            }
        }
    } else {
        // ---- fused gather directly into accumulators ----
        // stage (idx, 0.1*weight) for the 128 s-columns of this tile into smem
        float2* sIW = (float2*)s_pool;          // [128][32]
        #pragma unroll
        for (int t = 0; t < 16; ++t) {
            int e = tid + t * 256;              // 0..4095
            int sl = e >> 5, k = e & 31;
            int s = n0 + sl;
            int ix = 0; float w = 0.f;
            if (s < Nfull) {
                ix = slidx[(size_t)s * K_ + k];
                w  = slw  [(size_t)s * K_ + k] * SLM_SCALE;
            }
            sIW[e] = make_float2(__int_as_float(ix), w);
        }
        __syncthreads();

        #pragma unroll
        for (int j = 0; j < 8; ++j) {
            const float2* iw = sIW + (size_t)(c * 8 + j) * K_;
            #pragma unroll 4
            for (int k = 0; k < K_; ++k) {
                float2 p = iw[k];
                int ix = __float_as_int(p.x);
                const float4* vp = (const float4*)(g_vt + (size_t)ix * M_ + r * 8);
                float4 v0 = vp[0], v1 = vp[1];
                ull wd = pack2(p.y, p.y);
                ffma2(acc2[0][j], pack2(v0.x, v0.y), wd);
                ffma2(acc2[1][j], pack2(v0.z, v0.w), wd);
                ffma2(acc2[2][j], pack2(v1.x, v1.y), wd);
                ffma2(acc2[3][j], pack2(v1.z, v1.w), wd);
            }
        }

        // final store: out[m*S + n] = acc + b2   (S tail is a multiple of 8 -> per-thread guard)
        if (n0 + c * 8 < Nfull) {
            float bb[8];
            #pragma unroll
            for (int j = 0; j < 8; ++j) bb[j] = bias[n0 + c * 8 + j];
            float v[4][8][2];
            #pragma unroll
            for (int i2 = 0; i2 < 4; ++i2)
                #pragma unroll
                for (int j = 0; j < 8; ++j)
                    unpack2(acc2[i2][j], v[i2][j][0], v[i2][j][1]);
            #pragma unroll
            for (int i = 0; i < 8; ++i) {
                int m = r * 8 + i;
                float* dst = out + (size_t)m * Nfull + n0 + c * 8;
                int i2 = i >> 1, h = i & 1;
                *(float4*)dst = make_float4(v[i2][0][h] + bb[0], v[i2][1][h] + bb[1],
                                            v[i2][2][h] + bb[2], v[i2][3][h] + bb[3]);
                *(float4*)(dst + 4) = make_float4(v[i2][4][h] + bb[4], v[i2][5][h] + bb[5],
                                                  v[i2][6][h] + bb[6], v[i2][7][h] + bb[7]);
            }
        }
    }
}

// ---------------- launch ----------------
extern "C" void kernel_launch(void* const* d_in, const int* in_sizes, int n_in,
                              void* d_out, int out_size)
{
    const float* x     = (const float*)d_in[0];   // cached_embeddings [2,64,1024]
    const float* gamma = (const float*)d_in[1];   // bn_gamma [64]
    const float* beta  = (const float*)d_in[2];   // bn_beta  [64]
    const float* W1    = (const float*)d_in[3];   // [1024,512]
    const float* b1    = (const float*)d_in[4];   // [512]
    const float* W2    = (const float*)d_in[5];   // [512,50000]
    const float* b2    = (const float*)d_in[6];   // [50000]
    const float* Wslm  = (const float*)d_in[7];   // [512,40000]
    const float* bslm  = (const float*)d_in[8];   // [40000]
    const float* slw   = (const float*)d_in[9];   // [50000,32]
    const int*   slidx = (const int*)d_in[10];    // [50000,32]
    float* out = (float*)d_out;

    bn_stats_kernel<<<L_, 256>>>(x, gamma, beta);
    h_gemm_kernel<<<dim3(2, 16), 256>>>(x, W1, b1);
    big_gemm_kernel<0><<<(V_ + 127) / 128, 256>>>(Wslm, bslm, nullptr, nullptr, nullptr, V_);
    big_gemm_kernel<1><<<(S_ + 127) / 128, 256>>>(W2, b2, slw, slidx, out, S_);
}

// round 9
// speedup vs baseline: 1.8145x; 1.8145x over previous
#include <cuda_runtime.h>
#include <cuda_bf16.h>
#include <cstdint>

// Problem constants
#define B_      2
#define L_      64
#define D_      1024
#define H_      512
#define S_      50000
#define V_      40000
#define K_      32
#define M_      128          // B_*L_
#define SLM_SCALE 0.1f
#define BN_EPS  1e-5f

typedef unsigned long long ull;

// ---------------- f32x2 packed helpers ----------------
static __device__ __forceinline__ ull pack2(float x, float y) {
    ull r; asm("mov.b64 %0, {%1, %2};" : "=l"(r) : "f"(x), "f"(y)); return r;
}
static __device__ __forceinline__ void unpack2(ull v, float& x, float& y) {
    asm("mov.b64 {%0, %1}, %2;" : "=f"(x), "=f"(y) : "l"(v));
}
static __device__ __forceinline__ void ffma2(ull& d, ull a, ull b) {
    asm("fma.rn.f32x2 %0, %1, %2, %0;" : "+l"(d) : "l"(a), "l"(b));
}
static __device__ __forceinline__ void cpa16(uint32_t dst, const void* src, int bytes) {
    asm volatile("cp.async.cg.shared.global [%0], [%1], 16, %2;"
                 :: "r"(dst), "l"(src), "r"(bytes) : "memory");
}
static __device__ __forceinline__ void cpa_commit() {
    asm volatile("cp.async.commit_group;" ::: "memory");
}
static __device__ __forceinline__ void cpa_wait0() {
    asm volatile("cp.async.wait_group 0;" ::: "memory");
}

// ---------------- scratch (device globals; no allocation allowed) ----------------
__device__ float g_scale[L_];
__device__ float g_shift[L_];
__device__ __align__(16) float g_ht[H_ * M_];          // h^T : [512][128]
__device__ __align__(16) float g_vt[V_ * M_];          // v^T : [40000][128] (20.5 MB, L2-resident)

// ---------------- Kernel 1: BatchNorm stats over (B, D) per position l ----------------
__global__ __launch_bounds__(256)
void bn_stats_kernel(const float* __restrict__ x,
                     const float* __restrict__ gamma,
                     const float* __restrict__ beta)
{
    const int l = blockIdx.x;
    const float* p0 = x + (size_t)l * D_;             // b = 0
    const float* p1 = x + (size_t)(L_ + l) * D_;      // b = 1
    float s = 0.f, sq = 0.f;
    for (int i = threadIdx.x; i < D_; i += 256) {
        float a = p0[i], b = p1[i];
        s  += a + b;
        sq += a * a + b * b;
    }
    __shared__ float rs[256], rq[256];
    rs[threadIdx.x] = s; rq[threadIdx.x] = sq;
    __syncthreads();
    for (int off = 128; off > 0; off >>= 1) {
        if (threadIdx.x < off) {
            rs[threadIdx.x] += rs[threadIdx.x + off];
            rq[threadIdx.x] += rq[threadIdx.x + off];
        }
        __syncthreads();
    }
    if (threadIdx.x == 0) {
        const float inv_n = 1.f / (float)(B_ * D_);
        float mean = rs[0] * inv_n;
        float var  = rq[0] * inv_n - mean * mean;
        float rstd = rsqrtf(var + BN_EPS);
        float sc = gamma[l] * rstd;
        g_scale[l] = sc;
        g_shift[l] = beta[l] - mean * sc;
    }
}

// ---------------- Kernel 2: h = relu(xn @ W1 + b1), stored transposed ----------------
__global__ __launch_bounds__(256)
void h_gemm_kernel(const float* __restrict__ x,
                   const float* __restrict__ W1,
                   const float* __restrict__ b1)
{
    __shared__ float sSc[64], sSh[64];
    __shared__ float Ast[64 * 33];
    __shared__ float Bst[32 * 32];
    const int tid = threadIdx.x;
    const int m0 = blockIdx.x * 64;
    const int n0 = blockIdx.y * 32;
    if (tid < 64) { sSc[tid] = g_scale[tid]; sSh[tid] = g_shift[tid]; }
    __syncthreads();
    const int mg = tid >> 4;
    const int ng = tid & 15;
    float acc[4][2] = {};
    for (int k0 = 0; k0 < D_; k0 += 32) {
        #pragma unroll
        for (int i = 0; i < 8; ++i) {
            int e = tid + i * 256;
            int mi = e >> 5, ki = e & 31;
            float v = x[(size_t)(m0 + mi) * D_ + k0 + ki];
            Ast[mi * 33 + ki] = v * sSc[mi] + sSh[mi];
        }
        #pragma unroll
        for (int i = 0; i < 4; ++i) {
            int e = tid + i * 256;
            int ki = e >> 5, ni = e & 31;
            Bst[ki * 32 + ni] = W1[(size_t)(k0 + ki) * H_ + n0 + ni];
        }
        __syncthreads();
        #pragma unroll
        for (int kk = 0; kk < 32; ++kk) {
            float b0 = Bst[kk * 32 + ng * 2];
            float b1v = Bst[kk * 32 + ng * 2 + 1];
            #pragma unroll
            for (int i = 0; i < 4; ++i) {
                float a = Ast[(mg * 4 + i) * 33 + kk];
                acc[i][0] = fmaf(a, b0, acc[i][0]);
                acc[i][1] = fmaf(a, b1v, acc[i][1]);
            }
        }
        __syncthreads();
    }
    #pragma unroll
    for (int j = 0; j < 2; ++j) {
        int n = n0 + ng * 2 + j;
        float bb = b1[n];
        #pragma unroll
        for (int i = 0; i < 4; ++i) {
            int m = m0 + mg * 4 + i;
            float hv = acc[i][j] + bb;
            g_ht[(size_t)n * M_ + m] = fmaxf(hv, 0.f);
        }
    }
}

// ---------------- Kernels 3 & 4: big GEMMs via packed fma.rn.f32x2 ----------------
// 256 threads, block tile M=128 x N=64, KC=16, thread tile 8m x 4n.
// Accumulators packed along M (pairs align with LDS.128 result registers).
// cp.async double-buffered mainloop.
// MODE 0: v^T = (h @ W_slm + b_slm)^T   -> g_vt
// MODE 1: out = h @ W2 + b2 + 0.1 * gather(v^T)   (coalesced gather epilogue)
template<int MODE>
__global__ __launch_bounds__(256)
void big_gemm_kernel(const float* __restrict__ W,
                     const float* __restrict__ bias,
                     const float* __restrict__ slw,
                     const int*   __restrict__ slidx,
                     float* __restrict__ out,
                     int Nfull)
{
    constexpr int KC = 16;
    constexpr int BUF = KC * 128 + KC * 64;  // 3072 floats per stage
    // mode1 also reuses the pool as the 128x65 C-staging tile (8320 floats)
    __shared__ __align__(16) float s_pool[(MODE == 1) ? (128 * 65) : (2 * BUF)];
    __shared__ int   sIdx[8][32];
    __shared__ float sWt[8][32];

    const int tid = threadIdx.x;
    const int r = tid >> 4;           // 0..15 -> m base r*8
    const int c = tid & 15;           // 0..15 -> n base c*4
    const int n0 = blockIdx.x * 64;

    ull acc2[4][4];                   // [m-pair][n]
    #pragma unroll
    for (int i = 0; i < 4; ++i)
        #pragma unroll
        for (int j = 0; j < 4; ++j) acc2[i][j] = 0ULL;

    const uint32_t s_base = (uint32_t)__cvta_generic_to_shared(s_pool);

    // --- async stage issue: A tile KC x 128 (contiguous slab of g_ht), B tile KC x 64 ---
    auto issue = [&](int k0, int buf) {
        uint32_t sA = s_base + buf * (BUF * 4);
        uint32_t sB = sA + KC * 128 * 4;
        #pragma unroll
        for (int t = 0; t < 2; ++t) {
            int lin = tid + t * 256;                       // float4 index 0..511
            cpa16(sA + lin * 16, g_ht + (size_t)k0 * M_ + lin * 4, 16);
        }
        {
            int lin = tid;                                  // float4 index 0..255
            int ki = lin >> 4;
            int n  = n0 + (lin & 15) * 4;
            bool ok = (MODE == 0) || (n < Nfull);
            const float* src = W + (size_t)(k0 + ki) * Nfull + (ok ? n : 0);
            cpa16(sB + lin * 16, src, ok ? 16 : 0);
        }
        cpa_commit();
    };

    issue(0, 0);
    int buf = 0;
    for (int it = 0; it < H_ / KC; ++it) {
        cpa_wait0();
        __syncthreads();                       // everyone done with prev compute + this buf loaded
        if (it + 1 < H_ / KC) issue((it + 1) * KC, buf ^ 1);

        const float4* As4 = (const float4*)(s_pool + buf * BUF);
        const float4* Bs4 = (const float4*)(s_pool + buf * BUF + KC * 128);
        #pragma unroll
        for (int kk = 0; kk < KC; ++kk) {
            float4 a0 = As4[kk * 32 + r * 2];
            float4 a1 = As4[kk * 32 + r * 2 + 1];
            float4 b  = Bs4[kk * 16 + c];
            ull bd0 = pack2(b.x, b.x), bd1 = pack2(b.y, b.y);
            ull bd2 = pack2(b.z, b.z), bd3 = pack2(b.w, b.w);
            ull am;
            am = pack2(a0.x, a0.y);
            ffma2(acc2[0][0], am, bd0); ffma2(acc2[0][1], am, bd1);
            ffma2(acc2[0][2], am, bd2); ffma2(acc2[0][3], am, bd3);
            am = pack2(a0.z, a0.w);
            ffma2(acc2[1][0], am, bd0); ffma2(acc2[1][1], am, bd1);
            ffma2(acc2[1][2], am, bd2); ffma2(acc2[1][3], am, bd3);
            am = pack2(a1.x, a1.y);
            ffma2(acc2[2][0], am, bd0); ffma2(acc2[2][1], am, bd1);
            ffma2(acc2[2][2], am, bd2); ffma2(acc2[2][3], am, bd3);
            am = pack2(a1.z, a1.w);
            ffma2(acc2[3][0], am, bd0); ffma2(acc2[3][1], am, bd1);
            ffma2(acc2[3][2], am, bd2); ffma2(acc2[3][3], am, bd3);
        }
        buf ^= 1;
    }

    if (MODE == 0) {
        // store v^T (+ b_slm). V is an exact multiple of 64: no guards.
        #pragma unroll
        for (int j = 0; j < 4; ++j) {
            int n = n0 + c * 4 + j;
            float bs = bias[n];
            float x0, x1, x2, x3, x4, x5, x6, x7;
            unpack2(acc2[0][j], x0, x1);
            unpack2(acc2[1][j], x2, x3);
            unpack2(acc2[2][j], x4, x5);
            unpack2(acc2[3][j], x6, x7);
            float* dst = g_vt + (size_t)n * M_ + r * 8;
            *(float4*)dst       = make_float4(x0 + bs, x1 + bs, x2 + bs, x3 + bs);
            *(float4*)(dst + 4) = make_float4(x4 + bs, x5 + bs, x6 + bs, x7 + bs);
        }
    } else {
        // ---- stage C into smem, coalesced sparse gather-add, coalesced store ----
        __syncthreads();                       // all mainloop smem reads done before reuse
        float* Cs = s_pool;                    // 128 x 65 (padded)
        #pragma unroll
        for (int i2 = 0; i2 < 4; ++i2) {
            #pragma unroll
            for (int j = 0; j < 4; ++j) {
                float lo, hi;
                unpack2(acc2[i2][j], lo, hi);
                int col = c * 4 + j;
                Cs[(r * 8 + 2 * i2 + 0) * 65 + col] = lo;
                Cs[(r * 8 + 2 * i2 + 1) * 65 + col] = hi;
            }
        }
        __syncthreads();

        const int w = tid >> 5, ln = tid & 31;
        #pragma unroll 1
        for (int si = 0; si < 8; ++si) {
            int nl = w * 8 + si;
            int s = n0 + nl;
            if (s < Nfull) {                      // warp-uniform
                sIdx[w][ln] = slidx[(size_t)s * K_ + ln];
                sWt[w][ln]  = slw  [(size_t)s * K_ + ln] * SLM_SCALE;
                __syncwarp();
                float ax = 0.f, ay = 0.f, az = 0.f, aw = 0.f;
                #pragma unroll
                for (int k = 0; k < K_; ++k) {
                    int   ix = sIdx[w][k];
                    float wk = sWt[w][k];
                    // 512B coalesced per warp (lane ln covers m = 4*ln..4*ln+3)
                    float4 vv = *(const float4*)(g_vt + (size_t)ix * M_ + ln * 4);
                    ax = fmaf(wk, vv.x, ax);
                    ay = fmaf(wk, vv.y, ay);
                    az = fmaf(wk, vv.z, az);
                    aw = fmaf(wk, vv.w, aw);
                }
                int mB = ln * 4;
                Cs[(mB + 0) * 65 + nl] += ax;
                Cs[(mB + 1) * 65 + nl] += ay;
                Cs[(mB + 2) * 65 + nl] += az;
                Cs[(mB + 3) * 65 + nl] += aw;
                __syncwarp();
            }
        }
        __syncthreads();
        // coalesced final store: out[m*S + n] = y + b2 + 0.1*slm
        for (int e = tid; e < 128 * 64; e += 256) {
            int m = e >> 6, nl = e & 63;
            int n = n0 + nl;
            if (n < Nfull)
                out[(size_t)m * Nfull + n] = Cs[m * 65 + nl] + bias[n];
        }
    }
}

// ---------------- launch ----------------
extern "C" void kernel_launch(void* const* d_in, const int* in_sizes, int n_in,
                              void* d_out, int out_size)
{
    const float* x     = (const float*)d_in[0];   // cached_embeddings [2,64,1024]
    const float* gamma = (const float*)d_in[1];   // bn_gamma [64]
    const float* beta  = (const float*)d_in[2];   // bn_beta  [64]
    const float* W1    = (const float*)d_in[3];   // [1024,512]
    const float* b1    = (const float*)d_in[4];   // [512]
    const float* W2    = (const float*)d_in[5];   // [512,50000]
    const float* b2    = (const float*)d_in[6];   // [50000]
    const float* Wslm  = (const float*)d_in[7];   // [512,40000]
    const float* bslm  = (const float*)d_in[8];   // [40000]
    const float* slw   = (const float*)d_in[9];   // [50000,32]
    const int*   slidx = (const int*)d_in[10];    // [50000,32]
    float* out = (float*)d_out;

    bn_stats_kernel<<<L_, 256>>>(x, gamma, beta);
    h_gemm_kernel<<<dim3(2, 16), 256>>>(x, W1, b1);
    big_gemm_kernel<0><<<V_ / 64, 256>>>(Wslm, bslm, nullptr, nullptr, nullptr, V_);
    big_gemm_kernel<1><<<(S_ + 63) / 64, 256>>>(W2, b2, slw, slidx, out, S_);
}

// round 11
// speedup vs baseline: 2.3524x; 1.2964x over previous
#include <cuda_runtime.h>
#include <cuda_bf16.h>
#include <cstdint>

// Problem constants
#define B_      2
#define L_      64
#define D_      1024
#define H_      512
#define S_      50000
#define V_      40000
#define K_      32
#define M_      128          // B_*L_
#define SLM_SCALE 0.1f
#define BN_EPS  1e-5f

typedef unsigned long long ull;

// ---------------- PTX helpers (all target-suffix-free, valid on compute_103) ----------
static __device__ __forceinline__ void ldsm_x4(uint32_t* r, uint32_t addr) {
    asm volatile("ldmatrix.sync.aligned.m8n8.x4.shared.b16 {%0,%1,%2,%3}, [%4];"
                 : "=r"(r[0]), "=r"(r[1]), "=r"(r[2]), "=r"(r[3]) : "r"(addr));
}
static __device__ __forceinline__ void ldsm_x4_t(uint32_t* r, uint32_t addr) {
    asm volatile("ldmatrix.sync.aligned.m8n8.x4.trans.shared.b16 {%0,%1,%2,%3}, [%4];"
                 : "=r"(r[0]), "=r"(r[1]), "=r"(r[2]), "=r"(r[3]) : "r"(addr));
}
static __device__ __forceinline__ void mma16816(float* c, const uint32_t* a,
                                                uint32_t b0, uint32_t b1) {
    asm volatile("mma.sync.aligned.m16n8k16.row.col.f32.bf16.bf16.f32 "
                 "{%0,%1,%2,%3}, {%4,%5,%6,%7}, {%8,%9}, {%0,%1,%2,%3};"
                 : "+f"(c[0]), "+f"(c[1]), "+f"(c[2]), "+f"(c[3])
                 : "r"(a[0]), "r"(a[1]), "r"(a[2]), "r"(a[3]), "r"(b0), "r"(b1));
}
static __device__ __forceinline__ void cpa16(uint32_t dst, const void* src) {
    asm volatile("cp.async.cg.shared.global [%0], [%1], 16;" :: "r"(dst), "l"(src) : "memory");
}
static __device__ __forceinline__ void cpa_commit() {
    asm volatile("cp.async.commit_group;" ::: "memory");
}
static __device__ __forceinline__ void cpa_wait0() {
    asm volatile("cp.async.wait_group 0;" ::: "memory");
}
static __device__ __forceinline__ void sts64(uint32_t addr, uint32_t lo, uint32_t hi) {
    asm volatile("st.shared.v2.b32 [%0], {%1, %2};" :: "r"(addr), "r"(lo), "r"(hi) : "memory");
}

// ---------------- scratch (device globals; no allocation allowed) ----------------
__device__ float g_scale[L_];
__device__ float g_shift[L_];
// h as bf16 hi/lo, [128 m][512 k] row-major (k contiguous) — cp.async-ready
__device__ __align__(16) __nv_bfloat16 g_hhi[M_ * H_];
__device__ __align__(16) __nv_bfloat16 g_hlo[M_ * H_];
// v^T as bf16: [40000 n][128 m]
__device__ __align__(16) __nv_bfloat16 g_vt16[V_ * M_];

// ---------------- Kernel 1: BatchNorm stats ----------------
__global__ __launch_bounds__(256)
void bn_stats_kernel(const float* __restrict__ x,
                     const float* __restrict__ gamma,
                     const float* __restrict__ beta)
{
    const int l = blockIdx.x;
    const float* p0 = x + (size_t)l * D_;
    const float* p1 = x + (size_t)(L_ + l) * D_;
    float s = 0.f, sq = 0.f;
    for (int i = threadIdx.x; i < D_; i += 256) {
        float a = p0[i], b = p1[i];
        s  += a + b;
        sq += a * a + b * b;
    }
    __shared__ float rs[256], rq[256];
    rs[threadIdx.x] = s; rq[threadIdx.x] = sq;
    __syncthreads();
    for (int off = 128; off > 0; off >>= 1) {
        if (threadIdx.x < off) {
            rs[threadIdx.x] += rs[threadIdx.x + off];
            rq[threadIdx.x] += rq[threadIdx.x + off];
        }
        __syncthreads();
    }
    if (threadIdx.x == 0) {
        const float inv_n = 1.f / (float)(B_ * D_);
        float mean = rs[0] * inv_n;
        float var  = rq[0] * inv_n - mean * mean;
        float rstd = rsqrtf(var + BN_EPS);
        float sc = gamma[l] * rstd;
        g_scale[l] = sc;
        g_shift[l] = beta[l] - mean * sc;
    }
}

// ---------------- Kernel 2: h = relu(xn @ W1 + b1) -> bf16 hi/lo [m][k] ----------------
__global__ __launch_bounds__(256)
void h_gemm_kernel(const float* __restrict__ x,
                   const float* __restrict__ W1,
                   const float* __restrict__ b1)
{
    __shared__ float sSc[64], sSh[64];
    __shared__ float Ast[64 * 33];
    __shared__ float Bst[32 * 32];
    const int tid = threadIdx.x;
    const int m0 = blockIdx.x * 64;
    const int n0 = blockIdx.y * 32;
    if (tid < 64) { sSc[tid] = g_scale[tid]; sSh[tid] = g_shift[tid]; }
    __syncthreads();
    const int mg = tid >> 4;
    const int ng = tid & 15;
    float acc[4][2] = {};
    for (int k0 = 0; k0 < D_; k0 += 32) {
        #pragma unroll
        for (int i = 0; i < 8; ++i) {
            int e = tid + i * 256;
            int mi = e >> 5, ki = e & 31;
            float v = x[(size_t)(m0 + mi) * D_ + k0 + ki];
            Ast[mi * 33 + ki] = v * sSc[mi] + sSh[mi];
        }
        #pragma unroll
        for (int i = 0; i < 4; ++i) {
            int e = tid + i * 256;
            int ki = e >> 5, ni = e & 31;
            Bst[ki * 32 + ni] = W1[(size_t)(k0 + ki) * H_ + n0 + ni];
        }
        __syncthreads();
        #pragma unroll
        for (int kk = 0; kk < 32; ++kk) {
            float b0 = Bst[kk * 32 + ng * 2];
            float b1v = Bst[kk * 32 + ng * 2 + 1];
            #pragma unroll
            for (int i = 0; i < 4; ++i) {
                float a = Ast[(mg * 4 + i) * 33 + kk];
                acc[i][0] = fmaf(a, b0, acc[i][0]);
                acc[i][1] = fmaf(a, b1v, acc[i][1]);
            }
        }
        __syncthreads();
    }
    #pragma unroll
    for (int j = 0; j < 2; ++j) {
        int n = n0 + ng * 2 + j;          // hidden index = k of big GEMMs
        float bb = b1[n];
        #pragma unroll
        for (int i = 0; i < 4; ++i) {
            int m = m0 + mg * 4 + i;
            float hv = fmaxf(acc[i][j] + bb, 0.f);
            __nv_bfloat16 hi = __float2bfloat16(hv);
            __nv_bfloat16 lo = __float2bfloat16(hv - __bfloat162float(hi));
            g_hhi[(size_t)m * H_ + n] = hi;
            g_hlo[(size_t)m * H_ + n] = lo;
        }
    }
}

// ---------------- Kernels 3 & 4: bf16 hi/lo split GEMM via mma.sync (HMMA) -------------
// 256 threads (8 warps as 2m x 4n), block tile M=128 x N=64, K chunk 64 (8 chunks).
// Smem (single-buffered; 2 CTAs/SM give cross-CTA overlap):
//   Ah [128][72] bf16 (18,432 B)   Al (+18,432)
//   Bh [64][72]  bf16 ( 9,216 B)   Bl (+9,216)      total 55,296 B
// Padded 144B rows -> conflict-free ldmatrix. B stored k-major [k][n]; read via
// ldmatrix.x4.trans. 3-MMA split: hi*hi + hi*lo + lo*hi into fp32 accumulators.
// MODE 0: g_vt16[n][m] = bf16(h @ W_slm + b_slm)
// MODE 1: out = h @ W2 + b2 + 0.1 * gather(g_vt16)
#define RS 72        // padded row length (bf16 units); 144 bytes
template<int MODE>
__global__ __launch_bounds__(256, 2)
void mma_gemm_kernel(const float* __restrict__ W,
                     const float* __restrict__ bias,
                     const float* __restrict__ slw,
                     const int*   __restrict__ slidx,
                     float* __restrict__ out,
                     int Nfull)
{
    extern __shared__ __align__(16) unsigned char dynsmem[];
    __shared__ int   sIdx[8][32];
    __shared__ float sWt[8][32];

    const int tid = threadIdx.x;
    const int wid = tid >> 5;
    const int lid = tid & 31;
    const int wm = wid >> 2;            // 0..1  -> m offset wm*64
    const int wn = wid & 3;             // 0..3  -> n offset wn*16
    const int n0 = blockIdx.x * 64;

    const uint32_t sb = (uint32_t)__cvta_generic_to_shared(dynsmem);
    const uint32_t sAh = sb;
    const uint32_t sAl = sb + 128 * RS * 2;
    const uint32_t sBh = sAl + 128 * RS * 2;
    const uint32_t sBl = sBh + 64 * RS * 2;

    float acc[4][2][4];
    #pragma unroll
    for (int t = 0; t < 4; ++t)
        #pragma unroll
        for (int u = 0; u < 2; ++u)
            #pragma unroll
            for (int q = 0; q < 4; ++q) acc[t][u][q] = 0.f;

    for (int c = 0; c < 8; ++c) {
        const int k0 = c * 64;
        // ---- A: cp.async 16B granules from bf16 global images ----
        #pragma unroll
        for (int t = 0; t < 4; ++t) {
            int e = tid + t * 256;                 // 0..1023
            int m = e >> 3, g = e & 7;
            uint32_t d = m * (RS * 2) + g * 16;
            const char* srch = (const char*)g_hhi + (size_t)m * (H_ * 2) + k0 * 2 + g * 16;
            const char* srcl = (const char*)g_hlo + (size_t)m * (H_ * 2) + k0 * 2 + g * 16;
            cpa16(sAh + d, srch);
            cpa16(sAl + d, srcl);
        }
        cpa_commit();

        // ---- B: LDG fp32 (coalesced float4 along n), split hi/lo, store k-major ----
        const float* Wc = W + (size_t)k0 * Nfull;
        #pragma unroll
        for (int it = 0; it < 4; ++it) {
            int e4 = tid + it * 256;               // 0..1023
            int k  = e4 >> 4;
            int n4 = (e4 & 15) * 4;
            int gn = n0 + n4;
            float4 wv = make_float4(0.f, 0.f, 0.f, 0.f);
            if (MODE == 0 || gn + 3 < Nfull) {
                wv = *(const float4*)(Wc + (size_t)k * Nfull + gn);
            } else if (gn < Nfull) {
                float tmp[4] = {0.f, 0.f, 0.f, 0.f};
                #pragma unroll
                for (int j = 0; j < 4; ++j)
                    if (gn + j < Nfull) tmp[j] = Wc[(size_t)k * Nfull + gn + j];
                wv = make_float4(tmp[0], tmp[1], tmp[2], tmp[3]);
            }
            __nv_bfloat162 h01 = __floats2bfloat162_rn(wv.x, wv.y);
            __nv_bfloat162 h23 = __floats2bfloat162_rn(wv.z, wv.w);
            float2 fh01 = __bfloat1622float2(h01);
            float2 fh23 = __bfloat1622float2(h23);
            __nv_bfloat162 l01 = __floats2bfloat162_rn(wv.x - fh01.x, wv.y - fh01.y);
            __nv_bfloat162 l23 = __floats2bfloat162_rn(wv.z - fh23.x, wv.w - fh23.y);
            uint32_t d = k * (RS * 2) + n4 * 2;
            sts64(sBh + d, *reinterpret_cast<uint32_t*>(&h01), *reinterpret_cast<uint32_t*>(&h23));
            sts64(sBl + d, *reinterpret_cast<uint32_t*>(&l01), *reinterpret_cast<uint32_t*>(&l23));
        }
        cpa_wait0();
        __syncthreads();

        // ---- compute: 4 k16 steps ----
        #pragma unroll
        for (int ks = 0; ks < 4; ++ks) {
            // B fragments: two n8 tiles (this warp's n quarter), hi & lo
            uint32_t baddr = (uint32_t)((ks * 16 + (lid & 7) + ((lid >> 3) & 1) * 8) * (RS * 2)
                                        + (wn * 16 + (lid >> 4) * 8) * 2);
            uint32_t bh[4], bl[4];
            ldsm_x4_t(bh, sBh + baddr);
            ldsm_x4_t(bl, sBl + baddr);
            #pragma unroll
            for (int t = 0; t < 4; ++t) {
                uint32_t aaddr = (uint32_t)((wm * 64 + t * 16 + (lid & 15)) * (RS * 2)
                                            + (ks * 16 + (lid >> 4) * 8) * 2);
                uint32_t ah[4], al[4];
                ldsm_x4(ah, sAh + aaddr);
                ldsm_x4(al, sAl + aaddr);
                mma16816(acc[t][0], ah, bh[0], bh[1]);
                mma16816(acc[t][0], ah, bl[0], bl[1]);
                mma16816(acc[t][0], al, bh[0], bh[1]);
                mma16816(acc[t][1], ah, bh[2], bh[3]);
                mma16816(acc[t][1], ah, bl[2], bl[3]);
                mma16816(acc[t][1], al, bh[2], bh[3]);
            }
        }
        __syncthreads();      // before next chunk's fill overwrites smem
    }

    // ---------------- epilogues (reuse dynsmem) ----------------
    if (MODE == 0) {
        float* Ct = (float*)dynsmem;               // [64 n][132 m]
        #pragma unroll
        for (int t = 0; t < 4; ++t)
            #pragma unroll
            for (int u = 0; u < 2; ++u) {
                int row = wm * 64 + t * 16 + (lid >> 2);
                int col = wn * 16 + u * 8 + (lid & 3) * 2;
                Ct[(col    ) * 132 + row    ] = acc[t][u][0];
                Ct[(col + 1) * 132 + row    ] = acc[t][u][1];
                Ct[(col    ) * 132 + row + 8] = acc[t][u][2];
                Ct[(col + 1) * 132 + row + 8] = acc[t][u][3];
            }
        __syncthreads();
        #pragma unroll
        for (int it = 0; it < 8; ++it) {
            int e = tid + it * 256;                // 64 n x 32 m-quads
            int nl = e >> 5, mu = (e & 31) * 4;
            float bs = bias[n0 + nl];
            float4 v = *(const float4*)&Ct[nl * 132 + mu];
            __nv_bfloat162 p0 = __floats2bfloat162_rn(v.x + bs, v.y + bs);
            __nv_bfloat162 p1 = __floats2bfloat162_rn(v.z + bs, v.w + bs);
            uint2 pk;
            pk.x = *reinterpret_cast<uint32_t*>(&p0);
            pk.y = *reinterpret_cast<uint32_t*>(&p1);
            *(uint2*)(g_vt16 + (size_t)(n0 + nl) * M_ + mu) = pk;
        }
    } else {
        float* Cs = (float*)dynsmem;               // [128 m][65 n]
        #pragma unroll
        for (int t = 0; t < 4; ++t)
            #pragma unroll
            for (int u = 0; u < 2; ++u) {
                int row = wm * 64 + t * 16 + (lid >> 2);
                int col = wn * 16 + u * 8 + (lid & 3) * 2;
                Cs[(row    ) * 65 + col    ] = acc[t][u][0];
                Cs[(row    ) * 65 + col + 1] = acc[t][u][1];
                Cs[(row + 8) * 65 + col    ] = acc[t][u][2];
                Cs[(row + 8) * 65 + col + 1] = acc[t][u][3];
            }
        __syncthreads();

        // coalesced sparse gather-add (proven R8 epilogue)
        #pragma unroll 1
        for (int si = 0; si < 8; ++si) {
            int nl = wid * 8 + si;
            int s = n0 + nl;
            if (s < Nfull) {                       // warp-uniform
                sIdx[wid][lid] = slidx[(size_t)s * K_ + lid];
                sWt[wid][lid]  = slw  [(size_t)s * K_ + lid] * SLM_SCALE;
                __syncwarp();
                float ax = 0.f, ay = 0.f, az = 0.f, aw = 0.f;
                #pragma unroll
                for (int k = 0; k < K_; ++k) {
                    int   ix = sIdx[wid][k];
                    float wk = sWt[wid][k];
                    uint2 pk = *(const uint2*)(g_vt16 + (size_t)ix * M_ + lid * 4);
                    __nv_bfloat162 q0 = *reinterpret_cast<__nv_bfloat162*>(&pk.x);
                    __nv_bfloat162 q1 = *reinterpret_cast<__nv_bfloat162*>(&pk.y);
                    float2 f0 = __bfloat1622float2(q0);
                    float2 f1 = __bfloat1622float2(q1);
                    ax = fmaf(wk, f0.x, ax);
                    ay = fmaf(wk, f0.y, ay);
                    az = fmaf(wk, f1.x, az);
                    aw = fmaf(wk, f1.y, aw);
                }
                int mB = lid * 4;
                Cs[(mB + 0) * 65 + nl] += ax;
                Cs[(mB + 1) * 65 + nl] += ay;
                Cs[(mB + 2) * 65 + nl] += az;
                Cs[(mB + 3) * 65 + nl] += aw;
                __syncwarp();
            }
        }
        __syncthreads();
        for (int e = tid; e < 128 * 64; e += 256) {
            int m = e >> 6, nl = e & 63;
            int n = n0 + nl;
            if (n < Nfull)
                out[(size_t)m * Nfull + n] = Cs[m * 65 + nl] + bias[n];
        }
    }
}

// ---------------- launch ----------------
extern "C" void kernel_launch(void* const* d_in, const int* in_sizes, int n_in,
                              void* d_out, int out_size)
{
    const float* x     = (const float*)d_in[0];   // cached_embeddings [2,64,1024]
    const float* gamma = (const float*)d_in[1];   // bn_gamma [64]
    const float* beta  = (const float*)d_in[2];   // bn_beta  [64]
    const float* W1    = (const float*)d_in[3];   // [1024,512]
    const float* b1    = (const float*)d_in[4];   // [512]
    const float* W2    = (const float*)d_in[5];   // [512,50000]
    const float* b2    = (const float*)d_in[6];   // [50000]
    const float* Wslm  = (const float*)d_in[7];   // [512,40000]
    const float* bslm  = (const float*)d_in[8];   // [40000]
    const float* slw   = (const float*)d_in[9];   // [50000,32]
    const int*   slidx = (const int*)d_in[10];    // [50000,32]
    float* out = (float*)d_out;

    const int DYN = (128 * RS * 2 + 64 * RS * 2) * 2;   // 55,296 B
    cudaFuncSetAttribute(mma_gemm_kernel<0>, cudaFuncAttributeMaxDynamicSharedMemorySize, DYN);
    cudaFuncSetAttribute(mma_gemm_kernel<1>, cudaFuncAttributeMaxDynamicSharedMemorySize, DYN);

    bn_stats_kernel<<<L_, 256>>>(x, gamma, beta);
    h_gemm_kernel<<<dim3(2, 16), 256>>>(x, W1, b1);
    mma_gemm_kernel<0><<<V_ / 64, 256, DYN>>>(Wslm, bslm, nullptr, nullptr, nullptr, V_);
    mma_gemm_kernel<1><<<(S_ + 63) / 64, 256, DYN>>>(W2, b2, slw, slidx, out, S_);
}

// round 12
// speedup vs baseline: 2.5919x; 1.1018x over previous
#include <cuda_runtime.h>
#include <cuda_bf16.h>
#include <cstdint>

// Problem constants
#define B_      2
#define L_      64
#define D_      1024
#define H_      512
#define S_      50000
#define V_      40000
#define K_      32
#define M_      128          // B_*L_
#define SLM_SCALE 0.1f
#define BN_EPS  1e-5f

typedef unsigned long long ull;

// ---------------- PTX helpers (target-suffix-free; valid on compute_103) ----------
static __device__ __forceinline__ void ldsm_x4(uint32_t* r, uint32_t addr) {
    asm volatile("ldmatrix.sync.aligned.m8n8.x4.shared.b16 {%0,%1,%2,%3}, [%4];"
                 : "=r"(r[0]), "=r"(r[1]), "=r"(r[2]), "=r"(r[3]) : "r"(addr));
}
static __device__ __forceinline__ void ldsm_x4_t(uint32_t* r, uint32_t addr) {
    asm volatile("ldmatrix.sync.aligned.m8n8.x4.trans.shared.b16 {%0,%1,%2,%3}, [%4];"
                 : "=r"(r[0]), "=r"(r[1]), "=r"(r[2]), "=r"(r[3]) : "r"(addr));
}
static __device__ __forceinline__ void mma16816(float* c, const uint32_t* a,
                                                uint32_t b0, uint32_t b1) {
    asm volatile("mma.sync.aligned.m16n8k16.row.col.f32.bf16.bf16.f32 "
                 "{%0,%1,%2,%3}, {%4,%5,%6,%7}, {%8,%9}, {%0,%1,%2,%3};"
                 : "+f"(c[0]), "+f"(c[1]), "+f"(c[2]), "+f"(c[3])
                 : "r"(a[0]), "r"(a[1]), "r"(a[2]), "r"(a[3]), "r"(b0), "r"(b1));
}
static __device__ __forceinline__ void cpa16(uint32_t dst, const void* src) {
    asm volatile("cp.async.cg.shared.global [%0], [%1], 16;" :: "r"(dst), "l"(src) : "memory");
}
static __device__ __forceinline__ void cpa16z(uint32_t dst, const void* src, int bytes) {
    asm volatile("cp.async.cg.shared.global [%0], [%1], 16, %2;"
                 :: "r"(dst), "l"(src), "r"(bytes) : "memory");
}
static __device__ __forceinline__ void cpa_commit() {
    asm volatile("cp.async.commit_group;" ::: "memory");
}
static __device__ __forceinline__ void cpa_wait0() {
    asm volatile("cp.async.wait_group 0;" ::: "memory");
}
static __device__ __forceinline__ void sts64(uint32_t addr, uint32_t lo, uint32_t hi) {
    asm volatile("st.shared.v2.b32 [%0], {%1, %2};" :: "r"(addr), "r"(lo), "r"(hi) : "memory");
}

// ---------------- scratch (device globals; no allocation allowed) ----------------
__device__ float g_scale[L_];
__device__ float g_shift[L_];
// h as bf16 hi/lo, [128 m][512 k] row-major (k contiguous) — cp.async-ready
__device__ __align__(16) __nv_bfloat16 g_hhi[M_ * H_];
__device__ __align__(16) __nv_bfloat16 g_hlo[M_ * H_];
// v^T as bf16: [40000 n][128 m]
__device__ __align__(16) __nv_bfloat16 g_vt16[V_ * M_];

// ---------------- Kernel 1: BatchNorm stats ----------------
__global__ __launch_bounds__(256)
void bn_stats_kernel(const float* __restrict__ x,
                     const float* __restrict__ gamma,
                     const float* __restrict__ beta)
{
    const int l = blockIdx.x;
    const float* p0 = x + (size_t)l * D_;
    const float* p1 = x + (size_t)(L_ + l) * D_;
    float s = 0.f, sq = 0.f;
    for (int i = threadIdx.x; i < D_; i += 256) {
        float a = p0[i], b = p1[i];
        s  += a + b;
        sq += a * a + b * b;
    }
    __shared__ float rs[256], rq[256];
    rs[threadIdx.x] = s; rq[threadIdx.x] = sq;
    __syncthreads();
    for (int off = 128; off > 0; off >>= 1) {
        if (threadIdx.x < off) {
            rs[threadIdx.x] += rs[threadIdx.x + off];
            rq[threadIdx.x] += rq[threadIdx.x + off];
        }
        __syncthreads();
    }
    if (threadIdx.x == 0) {
        const float inv_n = 1.f / (float)(B_ * D_);
        float mean = rs[0] * inv_n;
        float var  = rq[0] * inv_n - mean * mean;
        float rstd = rsqrtf(var + BN_EPS);
        float sc = gamma[l] * rstd;
        g_scale[l] = sc;
        g_shift[l] = beta[l] - mean * sc;
    }
}

// ---------------- Kernel 2: h = relu(xn @ W1 + b1) -> bf16 hi/lo [m][k] ----------------
__global__ __launch_bounds__(256)
void h_gemm_kernel(const float* __restrict__ x,
                   const float* __restrict__ W1,
                   const float* __restrict__ b1)
{
    __shared__ float sSc[64], sSh[64];
    __shared__ float Ast[64 * 33];
    __shared__ float Bst[32 * 32];
    const int tid = threadIdx.x;
    const int m0 = blockIdx.x * 64;
    const int n0 = blockIdx.y * 32;
    if (tid < 64) { sSc[tid] = g_scale[tid]; sSh[tid] = g_shift[tid]; }
    __syncthreads();
    const int mg = tid >> 4;
    const int ng = tid & 15;
    float acc[4][2] = {};
    for (int k0 = 0; k0 < D_; k0 += 32) {
        #pragma unroll
        for (int i = 0; i < 8; ++i) {
            int e = tid + i * 256;
            int mi = e >> 5, ki = e & 31;
            float v = x[(size_t)(m0 + mi) * D_ + k0 + ki];
            Ast[mi * 33 + ki] = v * sSc[mi] + sSh[mi];
        }
        #pragma unroll
        for (int i = 0; i < 4; ++i) {
            int e = tid + i * 256;
            int ki = e >> 5, ni = e & 31;
            Bst[ki * 32 + ni] = W1[(size_t)(k0 + ki) * H_ + n0 + ni];
        }
        __syncthreads();
        #pragma unroll
        for (int kk = 0; kk < 32; ++kk) {
            float b0 = Bst[kk * 32 + ng * 2];
            float b1v = Bst[kk * 32 + ng * 2 + 1];
            #pragma unroll
            for (int i = 0; i < 4; ++i) {
                float a = Ast[(mg * 4 + i) * 33 + kk];
                acc[i][0] = fmaf(a, b0, acc[i][0]);
                acc[i][1] = fmaf(a, b1v, acc[i][1]);
            }
        }
        __syncthreads();
    }
    #pragma unroll
    for (int j = 0; j < 2; ++j) {
        int n = n0 + ng * 2 + j;          // hidden index = k of big GEMMs
        float bb = b1[n];
        #pragma unroll
        for (int i = 0; i < 4; ++i) {
            int m = m0 + mg * 4 + i;
            float hv = fmaxf(acc[i][j] + bb, 0.f);
            __nv_bfloat16 hi = __float2bfloat16(hv);
            __nv_bfloat16 lo = __float2bfloat16(hv - __bfloat162float(hi));
            g_hhi[(size_t)m * H_ + n] = hi;
            g_hlo[(size_t)m * H_ + n] = lo;
        }
    }
}

// ---------------- Kernels 3 & 4: double-buffered bf16 hi/lo HMMA GEMM ------------------
// 256 threads (8 warps: 2m x 4n), block tile M=128 x N=64, KC=32, 16 chunks.
// Per-stage smem (37,888 B; double-buffered = 75,776 B, 2 CTAs/SM):
//   +0      Ah [128 m][40] bf16 (80 B rows: 64 data + 16 pad)   10,240 B
//   +10240  Al                                                  10,240 B
//   +20480  Wraw [32 k][64 n] fp32 (cp.async raw)                8,192 B
//   +28672  Bh [32 k][72] bf16 (144 B rows: 128 data + 16 pad)   4,608 B
//   +33280  Bl                                                   4,608 B
// Pipeline: wait(c) -> bar -> issue(c+1) -> convert W(c)->B(c) -> bar -> MMA(c)
#define KC_    32
#define NCH    (H_ / KC_)          // 16
#define AROWB  80                  // A row bytes
#define BROWB  144                 // B row bytes
#define OFF_AL 10240
#define OFF_WR 20480
#define OFF_BH 28672
#define OFF_BL 33280
#define STG    37888

template<int MODE>
__global__ __launch_bounds__(256, 2)
void mma_gemm_kernel(const float* __restrict__ W,
                     const float* __restrict__ bias,
                     const float* __restrict__ slw,
                     const int*   __restrict__ slidx,
                     float* __restrict__ out,
                     int Nfull)
{
    extern __shared__ __align__(16) unsigned char dynsmem[];
    __shared__ int   sIdx[8][32];
    __shared__ float sWt[8][32];

    const int tid = threadIdx.x;
    const int wid = tid >> 5;
    const int lid = tid & 31;
    const int wm = wid >> 2;            // 0..1  -> m offset wm*64
    const int wn = wid & 3;             // 0..3  -> n offset wn*16
    const int n0 = blockIdx.x * 64;

    const uint32_t sb = (uint32_t)__cvta_generic_to_shared(dynsmem);

    float acc[4][2][4];
    #pragma unroll
    for (int t = 0; t < 4; ++t)
        #pragma unroll
        for (int u = 0; u < 2; ++u)
            #pragma unroll
            for (int q = 0; q < 4; ++q) acc[t][u][q] = 0.f;

    // ---- async fill of stage (A hi/lo bf16 + raw fp32 W) ----
    auto issue = [&](int c, int buf) {
        const uint32_t base = sb + buf * STG;
        const int k0b = c * KC_ * 2;             // byte offset into h rows
        #pragma unroll
        for (int t = 0; t < 2; ++t) {
            int e = tid + t * 256;               // 0..511
            int m = e >> 2, g = e & 3;
            uint32_t d = m * AROWB + g * 16;
            cpa16(base + d,          (const char*)g_hhi + (size_t)m * (H_ * 2) + k0b + g * 16);
            cpa16(base + OFF_AL + d, (const char*)g_hlo + (size_t)m * (H_ * 2) + k0b + g * 16);
        }
        const float* Wc = W + (size_t)(c * KC_) * Nfull;
        #pragma unroll
        for (int t = 0; t < 2; ++t) {
            int e = tid + t * 256;               // 0..511
            int k = e >> 4, n4 = (e & 15) * 4;
            int gn = n0 + n4;
            // Nfull % 4 == 0 -> each 16B granule is fully valid or fully OOB
            int bytes = (MODE == 0 || gn + 3 < Nfull) ? 16 : 0;
            cpa16z(base + OFF_WR + (k * 64 + n4) * 4, Wc + (size_t)k * Nfull + gn, bytes);
        }
        cpa_commit();
    };

    issue(0, 0);
    for (int c = 0; c < NCH; ++c) {
        const int buf = c & 1;
        const uint32_t base = sb + buf * STG;
        cpa_wait0();
        __syncthreads();                         // stage c resident; prev compute done
        if (c + 1 < NCH) issue(c + 1, buf ^ 1);

        // ---- convert raw W -> Bh/Bl (smem->smem, tiny) ----
        const float* wr = (const float*)(dynsmem + buf * STG + OFF_WR);
        #pragma unroll
        for (int t = 0; t < 2; ++t) {
            int e = tid + t * 256;               // 0..511
            int k = e >> 4, n4 = (e & 15) * 4;
            float4 wv = *(const float4*)(wr + k * 64 + n4);
            __nv_bfloat162 h01 = __floats2bfloat162_rn(wv.x, wv.y);
            __nv_bfloat162 h23 = __floats2bfloat162_rn(wv.z, wv.w);
            float2 fh01 = __bfloat1622float2(h01);
            float2 fh23 = __bfloat1622float2(h23);
            __nv_bfloat162 l01 = __floats2bfloat162_rn(wv.x - fh01.x, wv.y - fh01.y);
            __nv_bfloat162 l23 = __floats2bfloat162_rn(wv.z - fh23.x, wv.w - fh23.y);
            uint32_t d = k * BROWB + n4 * 2;
            sts64(base + OFF_BH + d, *reinterpret_cast<uint32_t*>(&h01),
                                     *reinterpret_cast<uint32_t*>(&h23));
            sts64(base + OFF_BL + d, *reinterpret_cast<uint32_t*>(&l01),
                                     *reinterpret_cast<uint32_t*>(&l23));
        }
        __syncthreads();                         // B tiles visible

        // ---- compute: 2 k16 steps x 4 m-tiles x 6 MMAs ----
        #pragma unroll
        for (int ks = 0; ks < 2; ++ks) {
            uint32_t baddr = base + OFF_BH
                + (uint32_t)((ks * 16 + (lid & 7) + ((lid >> 3) & 1) * 8) * BROWB
                             + (wn * 16 + (lid >> 4) * 8) * 2);
            uint32_t bh[4], bl[4];
            ldsm_x4_t(bh, baddr);
            ldsm_x4_t(bl, baddr + (OFF_BL - OFF_BH));
            #pragma unroll
            for (int t = 0; t < 4; ++t) {
                uint32_t aaddr = base
                    + (uint32_t)((wm * 64 + t * 16 + (lid & 15)) * AROWB
                                 + (ks * 16 + (lid >> 4) * 8) * 2);
                uint32_t ah[4], al[4];
                ldsm_x4(ah, aaddr);
                ldsm_x4(al, aaddr + OFF_AL);
                mma16816(acc[t][0], ah, bh[0], bh[1]);
                mma16816(acc[t][0], ah, bl[0], bl[1]);
                mma16816(acc[t][0], al, bh[0], bh[1]);
                mma16816(acc[t][1], ah, bh[2], bh[3]);
                mma16816(acc[t][1], ah, bl[2], bl[3]);
                mma16816(acc[t][1], al, bh[2], bh[3]);
            }
        }
    }
    __syncthreads();                             // mainloop smem dead

    // ---------------- epilogues (reuse dynsmem) ----------------
    if (MODE == 0) {
        float* Ct = (float*)dynsmem;               // [64 n][132 m]
        #pragma unroll
        for (int t = 0; t < 4; ++t)
            #pragma unroll
            for (int u = 0; u < 2; ++u) {
                int row = wm * 64 + t * 16 + (lid >> 2);
                int col = wn * 16 + u * 8 + (lid & 3) * 2;
                Ct[(col    ) * 132 + row    ] = acc[t][u][0];
                Ct[(col + 1) * 132 + row    ] = acc[t][u][1];
                Ct[(col    ) * 132 + row + 8] = acc[t][u][2];
                Ct[(col + 1) * 132 + row + 8] = acc[t][u][3];
            }
        __syncthreads();
        #pragma unroll
        for (int it = 0; it < 8; ++it) {
            int e = tid + it * 256;                // 64 n x 32 m-quads
            int nl = e >> 5, mu = (e & 31) * 4;
            float bs = bias[n0 + nl];
            float4 v = *(const float4*)&Ct[nl * 132 + mu];
            __nv_bfloat162 p0 = __floats2bfloat162_rn(v.x + bs, v.y + bs);
            __nv_bfloat162 p1 = __floats2bfloat162_rn(v.z + bs, v.w + bs);
            uint2 pk;
            pk.x = *reinterpret_cast<uint32_t*>(&p0);
            pk.y = *reinterpret_cast<uint32_t*>(&p1);
            *(uint2*)(g_vt16 + (size_t)(n0 + nl) * M_ + mu) = pk;
        }
    } else {
        float* Cs = (float*)dynsmem;               // [128 m][65 n]
        #pragma unroll
        for (int t = 0; t < 4; ++t)
            #pragma unroll
            for (int u = 0; u < 2; ++u) {
                int row = wm * 64 + t * 16 + (lid >> 2);
                int col = wn * 16 + u * 8 + (lid & 3) * 2;
                Cs[(row    ) * 65 + col    ] = acc[t][u][0];
                Cs[(row    ) * 65 + col + 1] = acc[t][u][1];
                Cs[(row + 8) * 65 + col    ] = acc[t][u][2];
                Cs[(row + 8) * 65 + col + 1] = acc[t][u][3];
            }
        __syncthreads();

        // coalesced sparse gather-add
        #pragma unroll 1
        for (int si = 0; si < 8; ++si) {
            int nl = wid * 8 + si;
            int s = n0 + nl;
            if (s < Nfull) {                       // warp-uniform
                sIdx[wid][lid] = slidx[(size_t)s * K_ + lid];
                sWt[wid][lid]  = slw  [(size_t)s * K_ + lid] * SLM_SCALE;
                __syncwarp();
                float ax = 0.f, ay = 0.f, az = 0.f, aw = 0.f;
                #pragma unroll
                for (int k = 0; k < K_; ++k) {
                    int   ix = sIdx[wid][k];
                    float wk = sWt[wid][k];
                    uint2 pk = *(const uint2*)(g_vt16 + (size_t)ix * M_ + lid * 4);
                    __nv_bfloat162 q0 = *reinterpret_cast<__nv_bfloat162*>(&pk.x);
                    __nv_bfloat162 q1 = *reinterpret_cast<__nv_bfloat162*>(&pk.y);
                    float2 f0 = __bfloat1622float2(q0);
                    float2 f1 = __bfloat1622float2(q1);
                    ax = fmaf(wk, f0.x, ax);
                    ay = fmaf(wk, f0.y, ay);
                    az = fmaf(wk, f1.x, az);
                    aw = fmaf(wk, f1.y, aw);
                }
                int mB = lid * 4;
                Cs[(mB + 0) * 65 + nl] += ax;
                Cs[(mB + 1) * 65 + nl] += ay;
                Cs[(mB + 2) * 65 + nl] += az;
                Cs[(mB + 3) * 65 + nl] += aw;
                __syncwarp();
            }
        }
        __syncthreads();
        for (int e = tid; e < 128 * 64; e += 256) {
            int m = e >> 6, nl = e & 63;
            int n = n0 + nl;
            if (n < Nfull)
                out[(size_t)m * Nfull + n] = Cs[m * 65 + nl] + bias[n];
        }
    }
}

// ---------------- launch ----------------
extern "C" void kernel_launch(void* const* d_in, const int* in_sizes, int n_in,
                              void* d_out, int out_size)
{
    const float* x     = (const float*)d_in[0];   // cached_embeddings [2,64,1024]
    const float* gamma = (const float*)d_in[1];   // bn_gamma [64]
    const float* beta  = (const float*)d_in[2];   // bn_beta  [64]
    const float* W1    = (const float*)d_in[3];   // [1024,512]
    const float* b1    = (const float*)d_in[4];   // [512]
    const float* W2    = (const float*)d_in[5];   // [512,50000]
    const float* b2    = (const float*)d_in[6];   // [50000]
    const float* Wslm  = (const float*)d_in[7];   // [512,40000]
    const float* bslm  = (const float*)d_in[8];   // [40000]
    const float* slw   = (const float*)d_in[9];   // [50000,32]
    const int*   slidx = (const int*)d_in[10];    // [50000,32]
    float* out = (float*)d_out;

    const int DYN = 2 * STG;                      // 75,776 B
    cudaFuncSetAttribute(mma_gemm_kernel<0>, cudaFuncAttributeMaxDynamicSharedMemorySize, DYN);
    cudaFuncSetAttribute(mma_gemm_kernel<1>, cudaFuncAttributeMaxDynamicSharedMemorySize, DYN);

    bn_stats_kernel<<<L_, 256>>>(x, gamma, beta);
    h_gemm_kernel<<<dim3(2, 16), 256>>>(x, W1, b1);
    mma_gemm_kernel<0><<<V_ / 64, 256, DYN>>>(Wslm, bslm, nullptr, nullptr, nullptr, V_);
    mma_gemm_kernel<1><<<(S_ + 63) / 64, 256, DYN>>>(W2, b2, slw, slidx, out, S_);
}

// round 13
// speedup vs baseline: 2.7482x; 1.0603x over previous
#include <cuda_runtime.h>
#include <cuda_bf16.h>
#include <cstdint>

// Problem constants
#define B_      2
#define L_      64
#define D_      1024
#define H_      512
#define S_      50000
#define V_      40000
#define K_      32
#define M_      128          // B_*L_
#define SLM_SCALE 0.1f
#define BN_EPS  1e-5f

typedef unsigned long long ull;

// ---------------- PTX helpers (target-suffix-free; valid on compute_103) ----------
static __device__ __forceinline__ void ldsm_x4(uint32_t* r, uint32_t addr) {
    asm volatile("ldmatrix.sync.aligned.m8n8.x4.shared.b16 {%0,%1,%2,%3}, [%4];"
                 : "=r"(r[0]), "=r"(r[1]), "=r"(r[2]), "=r"(r[3]) : "r"(addr));
}
static __device__ __forceinline__ void ldsm_x4_t(uint32_t* r, uint32_t addr) {
    asm volatile("ldmatrix.sync.aligned.m8n8.x4.trans.shared.b16 {%0,%1,%2,%3}, [%4];"
                 : "=r"(r[0]), "=r"(r[1]), "=r"(r[2]), "=r"(r[3]) : "r"(addr));
}
static __device__ __forceinline__ void mma16816(float* c, const uint32_t* a,
                                                uint32_t b0, uint32_t b1) {
    asm volatile("mma.sync.aligned.m16n8k16.row.col.f32.bf16.bf16.f32 "
                 "{%0,%1,%2,%3}, {%4,%5,%6,%7}, {%8,%9}, {%0,%1,%2,%3};"
                 : "+f"(c[0]), "+f"(c[1]), "+f"(c[2]), "+f"(c[3])
                 : "r"(a[0]), "r"(a[1]), "r"(a[2]), "r"(a[3]), "r"(b0), "r"(b1));
}
static __device__ __forceinline__ void cpa16(uint32_t dst, const void* src) {
    asm volatile("cp.async.cg.shared.global [%0], [%1], 16;" :: "r"(dst), "l"(src) : "memory");
}
static __device__ __forceinline__ void cpa_commit() {
    asm volatile("cp.async.commit_group;" ::: "memory");
}
static __device__ __forceinline__ void cpa_wait0() {
    asm volatile("cp.async.wait_group 0;" ::: "memory");
}
static __device__ __forceinline__ void sts64(uint32_t addr, uint32_t lo, uint32_t hi) {
    asm volatile("st.shared.v2.b32 [%0], {%1, %2};" :: "r"(addr), "r"(lo), "r"(hi) : "memory");
}

// ---------------- scratch (device globals; no allocation allowed) ----------------
__device__ float g_scale[L_];
__device__ float g_shift[L_];
// h as bf16 hi/lo, [128 m][512 k] row-major (k contiguous) — cp.async-ready
__device__ __align__(16) __nv_bfloat16 g_hhi[M_ * H_];
__device__ __align__(16) __nv_bfloat16 g_hlo[M_ * H_];
// v^T as bf16: [40000 n][128 m]
__device__ __align__(16) __nv_bfloat16 g_vt16[V_ * M_];

// ---------------- Kernel 1: BatchNorm stats ----------------
__global__ __launch_bounds__(256)
void bn_stats_kernel(const float* __restrict__ x,
                     const float* __restrict__ gamma,
                     const float* __restrict__ beta)
{
    const int l = blockIdx.x;
    const float* p0 = x + (size_t)l * D_;
    const float* p1 = x + (size_t)(L_ + l) * D_;
    float s = 0.f, sq = 0.f;
    for (int i = threadIdx.x; i < D_; i += 256) {
        float a = p0[i], b = p1[i];
        s  += a + b;
        sq += a * a + b * b;
    }
    __shared__ float rs[256], rq[256];
    rs[threadIdx.x] = s; rq[threadIdx.x] = sq;
    __syncthreads();
    for (int off = 128; off > 0; off >>= 1) {
        if (threadIdx.x < off) {
            rs[threadIdx.x] += rs[threadIdx.x + off];
            rq[threadIdx.x] += rq[threadIdx.x + off];
        }
        __syncthreads();
    }
    if (threadIdx.x == 0) {
        const float inv_n = 1.f / (float)(B_ * D_);
        float mean = rs[0] * inv_n;
        float var  = rq[0] * inv_n - mean * mean;
        float rstd = rsqrtf(var + BN_EPS);
        float sc = gamma[l] * rstd;
        g_scale[l] = sc;
        g_shift[l] = beta[l] - mean * sc;
    }
}

// ---------------- Kernel 2: h = relu(xn @ W1 + b1) -> bf16 hi/lo [m][k] ----------------
__global__ __launch_bounds__(256)
void h_gemm_kernel(const float* __restrict__ x,
                   const float* __restrict__ W1,
                   const float* __restrict__ b1)
{
    __shared__ float sSc[64], sSh[64];
    __shared__ float Ast[64 * 33];
    __shared__ float Bst[32 * 32];
    const int tid = threadIdx.x;
    const int m0 = blockIdx.x * 64;
    const int n0 = blockIdx.y * 32;
    if (tid < 64) { sSc[tid] = g_scale[tid]; sSh[tid] = g_shift[tid]; }
    __syncthreads();
    const int mg = tid >> 4;
    const int ng = tid & 15;
    float acc[4][2] = {};
    for (int k0 = 0; k0 < D_; k0 += 32) {
        #pragma unroll
        for (int i = 0; i < 8; ++i) {
            int e = tid + i * 256;
            int mi = e >> 5, ki = e & 31;
            float v = x[(size_t)(m0 + mi) * D_ + k0 + ki];
            Ast[mi * 33 + ki] = v * sSc[mi] + sSh[mi];
        }
        #pragma unroll
        for (int i = 0; i < 4; ++i) {
            int e = tid + i * 256;
            int ki = e >> 5, ni = e & 31;
            Bst[ki * 32 + ni] = W1[(size_t)(k0 + ki) * H_ + n0 + ni];
        }
        __syncthreads();
        #pragma unroll
        for (int kk = 0; kk < 32; ++kk) {
            float b0 = Bst[kk * 32 + ng * 2];
            float b1v = Bst[kk * 32 + ng * 2 + 1];
            #pragma unroll
            for (int i = 0; i < 4; ++i) {
                float a = Ast[(mg * 4 + i) * 33 + kk];
                acc[i][0] = fmaf(a, b0, acc[i][0]);
                acc[i][1] = fmaf(a, b1v, acc[i][1]);
            }
        }
        __syncthreads();
    }
    #pragma unroll
    for (int j = 0; j < 2; ++j) {
        int n = n0 + ng * 2 + j;          // hidden index = k of big GEMMs
        float bb = b1[n];
        #pragma unroll
        for (int i = 0; i < 4; ++i) {
            int m = m0 + mg * 4 + i;
            float hv = fmaxf(acc[i][j] + bb, 0.f);
            __nv_bfloat16 hi = __float2bfloat16(hv);
            __nv_bfloat16 lo = __float2bfloat16(hv - __bfloat162float(hi));
            g_hhi[(size_t)m * H_ + n] = hi;
            g_hlo[(size_t)m * H_ + n] = lo;
        }
    }
}

// ---------------- Kernels 3 & 4: 1-bar/chunk pipelined bf16 hi/lo HMMA GEMM ------------
// 256 threads (8 warps: 2m x 4n), block tile M=128 x N=64, KC=32, 16 chunks.
// Per-stage smem (29,696 B; 2 stages = 59,392 B, 2 CTAs/SM):
//   +0      Ah [128 m][40] bf16 (80 B rows)   10,240 B
//   +10240  Al                                10,240 B
//   +20480  Bh [32 k][72] bf16 (144 B rows)    4,608 B
//   +25088  Bl                                 4,608 B
// W path is register-resident per thread: LDG wreg(c+2) during MMA(c);
// STS-convert wreg(c+1)->B at top of chunk c (own data only -> no extra bar).
// Steady state: STS B(c+1) | MMA(c) | LDG wreg(c+2) | wait A(c+1) | bar | issue A(c+2).
#define KC_    32
#define NCH    (H_ / KC_)          // 16
#define AROWB  80
#define BROWB  144
#define OFF_AL 10240
#define OFF_BH 20480
#define OFF_BL 25088
#define STG    29696

template<int MODE>
__global__ __launch_bounds__(256, 2)
void mma_gemm_kernel(const float* __restrict__ W,
                     const float* __restrict__ bias,
                     const float* __restrict__ slw,
                     const int*   __restrict__ slidx,
                     float* __restrict__ out,
                     int Nfull)
{
    extern __shared__ __align__(16) unsigned char dynsmem[];
    __shared__ int   sIdx[8][32];
    __shared__ float sWt[8][32];

    const int tid = threadIdx.x;
    const int wid = tid >> 5;
    const int lid = tid & 31;
    const int wm = wid >> 2;            // 0..1  -> m offset wm*64
    const int wn = wid & 3;             // 0..3  -> n offset wn*16
    const int n0 = blockIdx.x * 64;

    const uint32_t sb = (uint32_t)__cvta_generic_to_shared(dynsmem);

    // this thread's W elements: two granules e0 = tid, e1 = tid + 256
    // granule e: k = e>>4, n4 = (e&15)*4
    const int k_a = tid >> 4,          n4_a = (tid & 15) * 4;
    const int k_b = (tid + 256) >> 4,  n4_b = (tid & 15) * 4;   // (e&15) same
    const bool okA = (MODE == 0) || (n0 + n4_a < Nfull);
    const bool okB = (MODE == 0) || (n0 + n4_b < Nfull);

    float4 wra, wrb;                    // W prefetch registers (chunk c+1)

    auto ldg_w = [&](int c) {
        const float* Wc = W + (size_t)(c * KC_) * Nfull + n0;
        wra = okA ? *(const float4*)(Wc + (size_t)k_a * Nfull + n4_a)
                  : make_float4(0.f, 0.f, 0.f, 0.f);
        wrb = okB ? *(const float4*)(Wc + (size_t)k_b * Nfull + n4_b)
                  : make_float4(0.f, 0.f, 0.f, 0.f);
    };
    auto sts_b = [&](int buf) {
        const uint32_t base = sb + buf * STG;
        #pragma unroll
        for (int t = 0; t < 2; ++t) {
            float4 wv = t ? wrb : wra;
            int k  = t ? k_b : k_a;
            int n4 = n4_a;
            __nv_bfloat162 h01 = __floats2bfloat162_rn(wv.x, wv.y);
            __nv_bfloat162 h23 = __floats2bfloat162_rn(wv.z, wv.w);
            float2 fh01 = __bfloat1622float2(h01);
            float2 fh23 = __bfloat1622float2(h23);
            __nv_bfloat162 l01 = __floats2bfloat162_rn(wv.x - fh01.x, wv.y - fh01.y);
            __nv_bfloat162 l23 = __floats2bfloat162_rn(wv.z - fh23.x, wv.w - fh23.y);
            uint32_t d = k * BROWB + n4 * 2;
            sts64(base + OFF_BH + d, *reinterpret_cast<uint32_t*>(&h01),
                                     *reinterpret_cast<uint32_t*>(&h23));
            sts64(base + OFF_BL + d, *reinterpret_cast<uint32_t*>(&l01),
                                     *reinterpret_cast<uint32_t*>(&l23));
        }
    };
    auto issue_a = [&](int c, int buf) {
        const uint32_t base = sb + buf * STG;
        const int k0b = c * KC_ * 2;
        #pragma unroll
        for (int t = 0; t < 2; ++t) {
            int e = tid + t * 256;               // 0..511
            int m = e >> 2, g = e & 3;
            uint32_t d = m * AROWB + g * 16;
            cpa16(base + d,          (const char*)g_hhi + (size_t)m * (H_ * 2) + k0b + g * 16);
            cpa16(base + OFF_AL + d, (const char*)g_hlo + (size_t)m * (H_ * 2) + k0b + g * 16);
        }
        cpa_commit();
    };

    float acc[4][2][4];
    #pragma unroll
    for (int t = 0; t < 4; ++t)
        #pragma unroll
        for (int u = 0; u < 2; ++u)
            #pragma unroll
            for (int q = 0; q < 4; ++q) acc[t][u][q] = 0.f;

    // ---- prologue ----
    ldg_w(0);
    sts_b(0);                 // B(0)
    issue_a(0, 0);
    ldg_w(1);
    cpa_wait0();              // A(0) complete (own granules)
    __syncthreads();          // A(0), B(0) visible to all
    issue_a(1, 1);

    for (int c = 0; c < NCH; ++c) {
        const int buf = c & 1;
        const uint32_t base = sb + buf * STG;

        if (c + 1 < NCH) sts_b((c + 1) & 1);     // publish B(c+1) (own regs)

        // ---- MMA(c): 2 k16 steps x 4 m-tiles x 6 MMAs ----
        #pragma unroll
        for (int ks = 0; ks < 2; ++ks) {
            uint32_t baddr = base + OFF_BH
                + (uint32_t)((ks * 16 + (lid & 7) + ((lid >> 3) & 1) * 8) * BROWB
                             + (wn * 16 + (lid >> 4) * 8) * 2);
            uint32_t bh[4], bl[4];
            ldsm_x4_t(bh, baddr);
            ldsm_x4_t(bl, baddr + (OFF_BL - OFF_BH));
            #pragma unroll
            for (int t = 0; t < 4; ++t) {
                uint32_t aaddr = base
                    + (uint32_t)((wm * 64 + t * 16 + (lid & 15)) * AROWB
                                 + (ks * 16 + (lid >> 4) * 8) * 2);
                uint32_t ah[4], al[4];
                ldsm_x4(ah, aaddr);
                ldsm_x4(al, aaddr + OFF_AL);
                mma16816(acc[t][0], ah, bh[0], bh[1]);
                mma16816(acc[t][0], ah, bl[0], bl[1]);
                mma16816(acc[t][0], al, bh[0], bh[1]);
                mma16816(acc[t][1], ah, bh[2], bh[3]);
                mma16816(acc[t][1], ah, bl[2], bl[3]);
                mma16816(acc[t][1], al, bh[2], bh[3]);
            }
        }

        if (c + 2 < NCH) ldg_w(c + 2);           // W prefetch for chunk c+2
        if (c + 1 < NCH) cpa_wait0();            // A(c+1) complete (own granules)
        __syncthreads();                         // rotate buffers; publish B(c+1)/A(c+1)
        if (c + 2 < NCH) issue_a(c + 2, buf);    // safe: A(c) readers done
    }

    // ---------------- epilogues (reuse dynsmem) ----------------
    if (MODE == 0) {
        float* Ct = (float*)dynsmem;               // [64 n][132 m]
        #pragma unroll
        for (int t = 0; t < 4; ++t)
            #pragma unroll
            for (int u = 0; u < 2; ++u) {
                int row = wm * 64 + t * 16 + (lid >> 2);
                int col = wn * 16 + u * 8 + (lid & 3) * 2;
                Ct[(col    ) * 132 + row    ] = acc[t][u][0];
                Ct[(col + 1) * 132 + row    ] = acc[t][u][1];
                Ct[(col    ) * 132 + row + 8] = acc[t][u][2];
                Ct[(col + 1) * 132 + row + 8] = acc[t][u][3];
            }
        __syncthreads();
        #pragma unroll
        for (int it = 0; it < 8; ++it) {
            int e = tid + it * 256;                // 64 n x 32 m-quads
            int nl = e >> 5, mu = (e & 31) * 4;
            float bs = bias[n0 + nl];
            float4 v = *(const float4*)&Ct[nl * 132 + mu];
            __nv_bfloat162 p0 = __floats2bfloat162_rn(v.x + bs, v.y + bs);
            __nv_bfloat162 p1 = __floats2bfloat162_rn(v.z + bs, v.w + bs);
            uint2 pk;
            pk.x = *reinterpret_cast<uint32_t*>(&p0);
            pk.y = *reinterpret_cast<uint32_t*>(&p1);
            *(uint2*)(g_vt16 + (size_t)(n0 + nl) * M_ + mu) = pk;
        }
    } else {
        float* Cs = (float*)dynsmem;               // [128 m][65 n]
        #pragma unroll
        for (int t = 0; t < 4; ++t)
            #pragma unroll
            for (int u = 0; u < 2; ++u) {
                int row = wm * 64 + t * 16 + (lid >> 2);
                int col = wn * 16 + u * 8 + (lid & 3) * 2;
                Cs[(row    ) * 65 + col    ] = acc[t][u][0];
                Cs[(row    ) * 65 + col + 1] = acc[t][u][1];
                Cs[(row + 8) * 65 + col    ] = acc[t][u][2];
                Cs[(row + 8) * 65 + col + 1] = acc[t][u][3];
            }
        __syncthreads();

        // coalesced sparse gather-add
        #pragma unroll 1
        for (int si = 0; si < 8; ++si) {
            int nl = wid * 8 + si;
            int s = n0 + nl;
            if (s < Nfull) {                       // warp-uniform
                sIdx[wid][lid] = slidx[(size_t)s * K_ + lid];
                sWt[wid][lid]  = slw  [(size_t)s * K_ + lid] * SLM_SCALE;
                __syncwarp();
                float ax = 0.f, ay = 0.f, az = 0.f, aw = 0.f;
                #pragma unroll
                for (int k = 0; k < K_; ++k) {
                    int   ix = sIdx[wid][k];
                    float wk = sWt[wid][k];
                    uint2 pk = *(const uint2*)(g_vt16 + (size_t)ix * M_ + lid * 4);
                    __nv_bfloat162 q0 = *reinterpret_cast<__nv_bfloat162*>(&pk.x);
                    __nv_bfloat162 q1 = *reinterpret_cast<__nv_bfloat162*>(&pk.y);
                    float2 f0 = __bfloat1622float2(q0);
                    float2 f1 = __bfloat1622float2(q1);
                    ax = fmaf(wk, f0.x, ax);
                    ay = fmaf(wk, f0.y, ay);
                    az = fmaf(wk, f1.x, az);
                    aw = fmaf(wk, f1.y, aw);
                }
                int mB = lid * 4;
                Cs[(mB + 0) * 65 + nl] += ax;
                Cs[(mB + 1) * 65 + nl] += ay;
                Cs[(mB + 2) * 65 + nl] += az;
                Cs[(mB + 3) * 65 + nl] += aw;
                __syncwarp();
            }
        }
        __syncthreads();
        for (int e = tid; e < 128 * 64; e += 256) {
            int m = e >> 6, nl = e & 63;
            int n = n0 + nl;
            if (n < Nfull)
                out[(size_t)m * Nfull + n] = Cs[m * 65 + nl] + bias[n];
        }
    }
}

// ---------------- launch ----------------
extern "C" void kernel_launch(void* const* d_in, const int* in_sizes, int n_in,
                              void* d_out, int out_size)
{
    const float* x     = (const float*)d_in[0];   // cached_embeddings [2,64,1024]
    const float* gamma = (const float*)d_in[1];   // bn_gamma [64]
    const float* beta  = (const float*)d_in[2];   // bn_beta  [64]
    const float* W1    = (const float*)d_in[3];   // [1024,512]
    const float* b1    = (const float*)d_in[4];   // [512]
    const float* W2    = (const float*)d_in[5];   // [512,50000]
    const float* b2    = (const float*)d_in[6];   // [50000]
    const float* Wslm  = (const float*)d_in[7];   // [512,40000]
    const float* bslm  = (const float*)d_in[8];   // [40000]
    const float* slw   = (const float*)d_in[9];   // [50000,32]
    const int*   slidx = (const int*)d_in[10];    // [50000,32]
    float* out = (float*)d_out;

    const int DYN = 2 * STG;                      // 59,392 B
    cudaFuncSetAttribute(mma_gemm_kernel<0>, cudaFuncAttributeMaxDynamicSharedMemorySize, DYN);
    cudaFuncSetAttribute(mma_gemm_kernel<1>, cudaFuncAttributeMaxDynamicSharedMemorySize, DYN);

    bn_stats_kernel<<<L_, 256>>>(x, gamma, beta);
    h_gemm_kernel<<<dim3(2, 16), 256>>>(x, W1, b1);
    mma_gemm_kernel<0><<<V_ / 64, 256, DYN>>>(Wslm, bslm, nullptr, nullptr, nullptr, V_);
    mma_gemm_kernel<1><<<(S_ + 63) / 64, 256, DYN>>>(W2, b2, slw, slidx, out, S_);
}